// round 13
// baseline (speedup 1.0000x reference)
#include <cuda_runtime.h>
#include <cuda_fp16.h>
#include <cstdint>

#define NN 16384
#define DD 64
#define SROW 128         // smem row stride bytes (data in 4 x 16B chunks + swizzle room)

constexpr float TAU_F   = 0.28f;
constexpr float EPS_F   = 1e-8f;
constexpr float LOG2E_F = 1.4426950408889634f;

// Scratch (allocation-free: __device__ globals)
__device__ int8_t g_a[NN * DD];               // int8 rows of a = u_n * log2e/TAU
__device__ int8_t g_b[NN * DD];               // int8 rows of w = u_n + i_n
__device__ float  g_sa[NN];                   // per-row scale of a
__device__ float  g_sw[NN];                   // per-row scale of w
__device__ float  g_pos[NN];
__device__ float  g_partial[(NN / 128) * NN]; // per-column-block partial row sums
__device__ float  g_blocksum[64];

__device__ __forceinline__ uint32_t smem_u32(const void* p) {
    uint32_t a;
    asm("{ .reg .u64 t; cvta.to.shared.u64 t, %1; cvt.u32.u64 %0, t; }" : "=r"(a) : "l"(p));
    return a;
}
__device__ __forceinline__ void cp16(uint32_t saddr, const void* g) {
    asm volatile("cp.async.cg.shared.global [%0], [%1], 16;" :: "r"(saddr), "l"(g));
}
__device__ __forceinline__ void ldsm_x4(uint32_t* r, uint32_t addr) {
    asm volatile("ldmatrix.sync.aligned.m8n8.x4.shared.b16 {%0,%1,%2,%3}, [%4];"
                 : "=r"(r[0]), "=r"(r[1]), "=r"(r[2]), "=r"(r[3]) : "r"(addr));
}
// int8 IMMA: m16n8k32, s32 accumulate (exact).
__device__ __forceinline__ void mma_s8(int* c, const uint32_t* a, uint32_t b0, uint32_t b1) {
    asm volatile(
        "mma.sync.aligned.m16n8k32.row.col.s32.s8.s8.s32 "
        "{%0,%1,%2,%3}, {%4,%5,%6,%7}, {%8,%9}, {%0,%1,%2,%3};"
        : "+r"(c[0]), "+r"(c[1]), "+r"(c[2]), "+r"(c[3])
        : "r"(a[0]), "r"(a[1]), "r"(a[2]), "r"(a[3]), "r"(b0), "r"(b1));
}
__device__ __forceinline__ uint32_t packh2(float x, float y) {
    uint32_t h;
    asm("cvt.rn.f16x2.f32 %0, %1, %2;" : "=r"(h) : "f"(y), "f"(x));
    return h;
}
__device__ __forceinline__ uint32_t ex2h2(uint32_t v) {
    uint32_t r;
    asm volatile("ex2.approx.f16x2 %0, %1;" : "=r"(r) : "r"(v));
    return r;
}
__device__ __forceinline__ uint32_t hadd2(uint32_t a, uint32_t b) {
    uint32_t r;
    asm("add.rn.f16x2 %0, %1, %2;" : "=r"(r) : "r"(a), "r"(b));
    return r;
}
__device__ __forceinline__ float unpack_sum(uint32_t v) {
    float lo, hi;
    asm("{ .reg .b16 l, h; mov.b32 {l, h}, %2;\n\t"
        "  cvt.f32.f16 %0, l; cvt.f32.f16 %1, h; }"
        : "=f"(lo), "=f"(hi) : "r"(v));
    return lo + hi;
}
// Swizzled physical chunk (16B units) for logical (row, chunk c in 0..3):
// 8 consecutive rows at fixed c hit 8 distinct chunk slots -> ldmatrix conflict-free.
__device__ __forceinline__ int pchunk(int row, int c) {
    return ((c ^ row) & 3) | (row & 4);
}

// ---------------------------------------------------------------------------
// Kernel 1: normalize, per-row int8 quantization of a = SC*u_n and w = u_n+i_n.
// Per-row scales via warp max (deterministic, no atomics).
// ---------------------------------------------------------------------------
__global__ void prep_kernel(const float* __restrict__ U, const float* __restrict__ I) {
    int row  = blockIdx.x * 8 + (threadIdx.x >> 5);
    int lane = threadIdx.x & 31;

    const float* up = U + (size_t)row * DD;
    const float* ip = I + (size_t)row * DD;
    float u0 = up[lane], u1 = up[lane + 32];
    float i0 = ip[lane], i1 = ip[lane + 32];

    float su = u0 * u0 + u1 * u1;
    float si = i0 * i0 + i1 * i1;
#pragma unroll
    for (int o = 16; o; o >>= 1) {
        su += __shfl_xor_sync(0xffffffffu, su, o);
        si += __shfl_xor_sync(0xffffffffu, si, o);
    }
    float inu = rsqrtf(fmaxf(su, 1e-24f));
    float ini = rsqrtf(fmaxf(si, 1e-24f));

    float un0 = u0 * inu, un1 = u1 * inu;
    float vn0 = i0 * ini, vn1 = i1 * ini;

    float d = un0 * vn0 + un1 * vn1;
#pragma unroll
    for (int o = 16; o; o >>= 1) d += __shfl_xor_sync(0xffffffffu, d, o);

    const float SC = LOG2E_F / TAU_F;
    float a0 = un0 * SC, a1 = un1 * SC;
    float w0 = un0 + vn0, w1 = un1 + vn1;

    float ma = fmaxf(fabsf(a0), fabsf(a1));
    float mw = fmaxf(fabsf(w0), fabsf(w1));
#pragma unroll
    for (int o = 16; o; o >>= 1) {
        ma = fmaxf(ma, __shfl_xor_sync(0xffffffffu, ma, o));
        mw = fmaxf(mw, __shfl_xor_sync(0xffffffffu, mw, o));
    }
    ma = fmaxf(ma, 1e-20f);
    mw = fmaxf(mw, 1e-20f);
    float inva = 127.0f / ma, invw = 127.0f / mw;

    size_t base = (size_t)row * DD;
    g_a[base + lane]      = (int8_t)__float2int_rn(a0 * inva);
    g_a[base + 32 + lane] = (int8_t)__float2int_rn(a1 * inva);
    g_b[base + lane]      = (int8_t)__float2int_rn(w0 * invw);
    g_b[base + 32 + lane] = (int8_t)__float2int_rn(w1 * invw);

    if (lane == 0) {
        g_sa[row]  = ma * (1.0f / 127.0f);
        g_sw[row]  = mw * (1.0f / 127.0f);
        g_pos[row] = d * (1.0f / TAU_F);
    }
}

// ---------------------------------------------------------------------------
// Kernel 2: int8 IMMA GEMM (m16n8k32, s32 exact acc), 128x128 tile, K=64.
// Dequant (per-row x per-col scale) + ex2.f16x2 + row-sum epilogue.
// 8 warps 2(M) x 4(N); warp tile 64x32.
// ---------------------------------------------------------------------------
__global__ void __launch_bounds__(256, 2) gemm_exp_kernel() {
    extern __shared__ __align__(16) char smem[];
    const uint32_t sb = smem_u32(smem);
    const uint32_t sA = sb;                    // 16 KB (128 rows x 128B padded)
    const uint32_t sB = sb + 128 * SROW;       // 16 KB

    const int tid  = threadIdx.x;
    const int wid  = tid >> 5;
    const int lane = tid & 31;
    const int wm   = wid >> 2;                 // 0..1
    const int wn   = wid & 3;                  // 0..3
    const int bm = blockIdx.y, bn = blockIdx.x;

    const char* Ag = (const char*)g_a + (size_t)bm * 128 * DD;
    const char* Bg = (const char*)g_b + (size_t)bn * 128 * DD;

    // Load both tiles: 128 rows x 4 chunks(16B) each operand (8 KB each).
#pragma unroll
    for (int it = 0; it < 2; it++) {
        int idx = it * 256 + tid;              // 0..511
        int row = idx >> 2;
        int c   = idx & 3;
        uint32_t so = (uint32_t)(row * SROW + pchunk(row, c) * 16);
        size_t   go = (size_t)row * DD + c * 16;
        cp16(sA + so, Ag + go);
        cp16(sB + so, Bg + go);
    }
    asm volatile("cp.async.commit_group;" ::: "memory");

    int acc[4][4][4];                          // s32 accumulators
#pragma unroll
    for (int i = 0; i < 4; i++)
#pragma unroll
        for (int j = 0; j < 4; j++)
#pragma unroll
            for (int r = 0; r < 4; r++) acc[i][j][r] = 0;

    asm volatile("cp.async.wait_group 0;" ::: "memory");
    __syncthreads();

#pragma unroll
    for (int s = 0; s < 2; s++) {              // 2 k32-steps (K=64)
        uint32_t a[4][4];
#pragma unroll
        for (int mf = 0; mf < 4; mf++) {
            int row = wm * 64 + mf * 16 + (lane & 7) + ((lane >> 3) & 1) * 8;
            int c   = 2 * s + (lane >> 4);
            ldsm_x4(a[mf], sA + row * SROW + pchunk(row, c) * 16);
        }
        uint32_t b[2][4];
#pragma unroll
        for (int p = 0; p < 2; p++) {
            int row = wn * 32 + p * 16 + (lane & 7) + ((lane >> 4) & 1) * 8;
            int c   = 2 * s + ((lane >> 3) & 1);
            ldsm_x4(b[p], sB + row * SROW + pchunk(row, c) * 16);
        }
        // b[p] = {b0(nf=2p), b1(nf=2p), b0(nf=2p+1), b1(nf=2p+1)}
#pragma unroll
        for (int mf = 0; mf < 4; mf++) {
            mma_s8(acc[mf][0], a[mf], b[0][0], b[0][1]);
            mma_s8(acc[mf][1], a[mf], b[0][2], b[0][3]);
            mma_s8(acc[mf][2], a[mf], b[1][0], b[1][1]);
            mma_s8(acc[mf][3], a[mf], b[1][2], b[1][3]);
        }
    }

    // ------- Epilogue: dequant + ex2.f16x2 + row sums -------
    // acc[mf][nf] = {c0:(row g, col 2t4), c1:(g, 2t4+1), c2:(g+8, 2t4), c3:(g+8, 2t4+1)}
    const int g  = lane >> 2;
    const int t4 = lane & 3;

    // Per-column scales for this thread's 8 columns (float2 pairs), L2-hot.
    float2 swv[4];
#pragma unroll
    for (int nf = 0; nf < 4; nf++)
        swv[nf] = *(const float2*)&g_sw[bn * 128 + wn * 32 + nf * 8 + 2 * t4];

    float rs0[4], rs1[4];
#pragma unroll
    for (int mf = 0; mf < 4; mf++) {
        float sa0 = g_sa[bm * 128 + wm * 64 + mf * 16 + g];
        float sa1 = g_sa[bm * 128 + wm * 64 + mf * 16 + g + 8];
        uint32_t e0[4], e1[4];
#pragma unroll
        for (int nf = 0; nf < 4; nf++) {
            float m00 = sa0 * swv[nf].x, m01 = sa0 * swv[nf].y;
            float m10 = sa1 * swv[nf].x, m11 = sa1 * swv[nf].y;
            float x0 = (float)acc[mf][nf][0] * m00;
            float x1 = (float)acc[mf][nf][1] * m01;
            float x2 = (float)acc[mf][nf][2] * m10;
            float x3 = (float)acc[mf][nf][3] * m11;
            e0[nf] = ex2h2(packh2(x0, x1));    // row g pair
            e1[nf] = ex2h2(packh2(x2, x3));    // row g+8 pair
        }
        uint32_t s0 = hadd2(hadd2(e0[0], e0[1]), hadd2(e0[2], e0[3]));
        uint32_t s1 = hadd2(hadd2(e1[0], e1[1]), hadd2(e1[2], e1[3]));
        rs0[mf] = unpack_sum(s0);
        rs1[mf] = unpack_sum(s1);
    }
#pragma unroll
    for (int mf = 0; mf < 4; mf++) {
        rs0[mf] += __shfl_xor_sync(0xffffffffu, rs0[mf], 1);
        rs0[mf] += __shfl_xor_sync(0xffffffffu, rs0[mf], 2);
        rs1[mf] += __shfl_xor_sync(0xffffffffu, rs1[mf], 1);
        rs1[mf] += __shfl_xor_sync(0xffffffffu, rs1[mf], 2);
    }

    __syncthreads();                           // tiles no longer needed; reuse smem
    float* red = (float*)smem;                 // [128 rows][4 wn]
    if (t4 == 0) {
#pragma unroll
        for (int mf = 0; mf < 4; mf++) {
            int r0 = wm * 64 + mf * 16 + g;
            red[r0 * 4 + wn]       = rs0[mf];
            red[(r0 + 8) * 4 + wn] = rs1[mf];
        }
    }
    __syncthreads();
    if (tid < 128) {
        float s = (red[tid * 4 + 0] + red[tid * 4 + 1]) +
                  (red[tid * 4 + 2] + red[tid * 4 + 3]);
        g_partial[(size_t)bn * NN + bm * 128 + tid] = s;   // fixed order, no atomics
    }
}

// ---------------------------------------------------------------------------
// Kernel 3: per-row total over 128 column-block partials, loss, block sums.
// ---------------------------------------------------------------------------
__global__ void reduce_kernel() {
    int r = blockIdx.x * blockDim.x + threadIdx.x;
    float t = 0.f;
#pragma unroll 8
    for (int cb = 0; cb < NN / 128; cb++) t += g_partial[(size_t)cb * NN + r];
    float lr = logf(t + EPS_F) - g_pos[r];

    __shared__ float sm[256];
    sm[threadIdx.x] = lr;
    __syncthreads();
    for (int o = 128; o; o >>= 1) {
        if (threadIdx.x < o) sm[threadIdx.x] += sm[threadIdx.x + o];
        __syncthreads();
    }
    if (threadIdx.x == 0) g_blocksum[blockIdx.x] = sm[0];
}

__global__ void final_kernel(float* __restrict__ out) {
    __shared__ float sm[64];
    int t = threadIdx.x;
    sm[t] = g_blocksum[t];
    __syncthreads();
    for (int o = 32; o; o >>= 1) {
        if (t < o) sm[t] += sm[t + o];
        __syncthreads();
    }
    if (t == 0) out[0] = sm[0] * (1.0f / (float)NN);
}

// ---------------------------------------------------------------------------
extern "C" void kernel_launch(void* const* d_in, const int* in_sizes, int n_in,
                              void* d_out, int out_size) {
    const float* U = (const float*)d_in[0];
    const float* I = (const float*)d_in[1];
    float* out = (float*)d_out;

    const int SMEM_BYTES = 2 * 128 * SROW;     // 32768
    cudaFuncSetAttribute(gemm_exp_kernel,
                         cudaFuncAttributeMaxDynamicSharedMemorySize, SMEM_BYTES);

    prep_kernel<<<NN / 8, 256>>>(U, I);

    dim3 grid(NN / 128, NN / 128);
    gemm_exp_kernel<<<grid, 256, SMEM_BYTES>>>();

    reduce_kernel<<<NN / 256, 256>>>();
    final_kernel<<<1, 64>>>(out);
}

// round 14
// speedup vs baseline: 2.2339x; 2.2339x over previous
#include <cuda_runtime.h>
#include <cuda_fp16.h>
#include <cstdint>

#define NN 16384
#define DD 64
#define KK 64            // plain fp16 GEMM: a . w (residual dropped)
#define SROW 128         // smem row stride bytes (8 x 16B chunks) for both operands

constexpr float TAU_F   = 0.28f;
constexpr float EPS_F   = 1e-8f;
constexpr float LOG2E_F = 1.4426950408889634f;

// Scratch (allocation-free: __device__ globals)
__device__ __half g_a[NN * KK];               // A rows: fp16(u_n * log2e/TAU)
__device__ __half g_b[NN * KK];               // B rows: fp16(u_n + i_n)
__device__ float g_pos[NN];
__device__ float g_partial[(NN / 128) * NN];  // per-column-block partial row sums
__device__ float g_blocksum[64];
__device__ int   g_done_cnt = 0;              // monotone counter for last-block detect

__device__ __forceinline__ uint32_t smem_u32(const void* p) {
    uint32_t a;
    asm("{ .reg .u64 t; cvta.to.shared.u64 t, %1; cvt.u32.u64 %0, t; }" : "=r"(a) : "l"(p));
    return a;
}
__device__ __forceinline__ void cp16(uint32_t saddr, const void* g) {
    asm volatile("cp.async.cg.shared.global [%0], [%1], 16;" :: "r"(saddr), "l"(g));
}
__device__ __forceinline__ void ldsm_x4(uint32_t* r, uint32_t addr) {
    asm volatile("ldmatrix.sync.aligned.m8n8.x4.shared.b16 {%0,%1,%2,%3}, [%4];"
                 : "=r"(r[0]), "=r"(r[1]), "=r"(r[2]), "=r"(r[3]) : "r"(addr));
}
// fp16-accumulator HMMA: D,C are 2 x f16x2 regs.
__device__ __forceinline__ void mma16816_f16(uint32_t* c, const uint32_t* a,
                                             uint32_t b0, uint32_t b1) {
    asm volatile(
        "mma.sync.aligned.m16n8k16.row.col.f16.f16.f16.f16 "
        "{%0,%1}, {%2,%3,%4,%5}, {%6,%7}, {%0,%1};"
        : "+r"(c[0]), "+r"(c[1])
        : "r"(a[0]), "r"(a[1]), "r"(a[2]), "r"(a[3]), "r"(b0), "r"(b1));
}
__device__ __forceinline__ uint32_t ex2h2(uint32_t v) {
    uint32_t r;
    asm volatile("ex2.approx.f16x2 %0, %1;" : "=r"(r) : "r"(v));
    return r;
}
__device__ __forceinline__ uint32_t hadd2(uint32_t a, uint32_t b) {
    uint32_t r;
    asm("add.rn.f16x2 %0, %1, %2;" : "=r"(r) : "r"(a), "r"(b));
    return r;
}
__device__ __forceinline__ float unpack_sum(uint32_t v) {
    float lo, hi;
    asm("{ .reg .b16 l, h; mov.b32 {l, h}, %2;\n\t"
        "  cvt.f32.f16 %0, l; cvt.f32.f16 %1, h; }"
        : "=f"(lo), "=f"(hi) : "r"(v));
    return lo + hi;
}

// ---------------------------------------------------------------------------
// Kernel 1: normalize, build fp16 A (scaled) and B (w = u_n + i_n).
// ---------------------------------------------------------------------------
__global__ void prep_kernel(const float* __restrict__ U, const float* __restrict__ I) {
    int row  = blockIdx.x * 8 + (threadIdx.x >> 5);
    int lane = threadIdx.x & 31;

    const float* up = U + (size_t)row * DD;
    const float* ip = I + (size_t)row * DD;
    float u0 = up[lane], u1 = up[lane + 32];
    float i0 = ip[lane], i1 = ip[lane + 32];

    float su = u0 * u0 + u1 * u1;
    float si = i0 * i0 + i1 * i1;
#pragma unroll
    for (int o = 16; o; o >>= 1) {
        su += __shfl_xor_sync(0xffffffffu, su, o);
        si += __shfl_xor_sync(0xffffffffu, si, o);
    }
    float inu = rsqrtf(fmaxf(su, 1e-24f));
    float ini = rsqrtf(fmaxf(si, 1e-24f));

    float un0 = u0 * inu, un1 = u1 * inu;
    float vn0 = i0 * ini, vn1 = i1 * ini;

    float d = un0 * vn0 + un1 * vn1;
#pragma unroll
    for (int o = 16; o; o >>= 1) d += __shfl_xor_sync(0xffffffffu, d, o);

    const float SC = LOG2E_F / TAU_F;   // GEMM output directly = log2 of each exp term
    size_t base = (size_t)row * KK;
    g_a[base + lane]      = __float2half_rn(un0 * SC);
    g_a[base + 32 + lane] = __float2half_rn(un1 * SC);
    g_b[base + lane]      = __float2half_rn(un0 + vn0);
    g_b[base + 32 + lane] = __float2half_rn(un1 + vn1);

    if (lane == 0) g_pos[row] = d * (1.0f / TAU_F);
}

// ---------------------------------------------------------------------------
// Kernel 2: fp16 mma.sync GEMM with fp16 accumulators, 128x128 tile, K=64.
// Epilogue: ex2.approx.f16x2 directly on packed accumulators + f16x2 partial
// sums -> fp32 row sums. 8 warps 2(M) x 4(N); warp tile 64x32. occ 3.
// ---------------------------------------------------------------------------
__global__ void __launch_bounds__(256, 3) gemm_exp_kernel() {
    extern __shared__ __align__(16) char smem[];
    const uint32_t sb = smem_u32(smem);
    const uint32_t sA = sb;                    // 16 KB
    const uint32_t sB = sb + 128 * SROW;       // 16 KB

    const int tid  = threadIdx.x;
    const int wid  = tid >> 5;
    const int lane = tid & 31;
    const int wm   = wid >> 2;                 // 0..1
    const int wn   = wid & 3;                  // 0..3
    const int bm = blockIdx.y, bn = blockIdx.x;

    const char* Ag = (const char*)g_a + (size_t)bm * 128 * (KK * 2);
    const char* Bg = (const char*)g_b + (size_t)bn * 128 * (KK * 2);

    // Load both tiles: 128 rows x 8 chunks(16B) each operand.
#pragma unroll
    for (int it = 0; it < 4; it++) {
        int idx = it * 256 + tid;              // 0..1023
        int row = idx >> 3;
        int c   = idx & 7;
        uint32_t sw = (uint32_t)(row * SROW + ((c ^ (row & 7)) << 4));
        size_t   go = (size_t)row * (KK * 2) + c * 16;
        cp16(sA + sw, Ag + go);
        cp16(sB + sw, Bg + go);
    }
    asm volatile("cp.async.commit_group;" ::: "memory");

    uint32_t acc[4][4][2];                     // f16x2 accumulators
#pragma unroll
    for (int i = 0; i < 4; i++)
#pragma unroll
        for (int j = 0; j < 4; j++) { acc[i][j][0] = 0u; acc[i][j][1] = 0u; }

    asm volatile("cp.async.wait_group 0;" ::: "memory");
    __syncthreads();

    const int lr16 = lane & 15;                // ldmatrix row within 16
    const int lhi  = lane >> 4;                // k-chunk half select

#pragma unroll
    for (int ks = 0; ks < KK / 16; ks++) {     // 4 k-steps
        const int ch = 2 * ks + lhi;           // 16B chunk index (0..7)
        uint32_t a[4][4];
#pragma unroll
        for (int mf = 0; mf < 4; mf++) {
            int row = wm * 64 + mf * 16 + lr16;
            ldsm_x4(a[mf], sA + row * SROW + ((ch ^ (row & 7)) << 4));
        }
        uint32_t bfr[2][4];
#pragma unroll
        for (int p = 0; p < 2; p++) {
            int row = wn * 32 + p * 16 + lr16;
            ldsm_x4(bfr[p], sB + row * SROW + ((ch ^ (row & 7)) << 4));
        }
        // bfr[p] = {b0(nf=2p), b0(nf=2p+1), b1(nf=2p), b1(nf=2p+1)}
#pragma unroll
        for (int mf = 0; mf < 4; mf++) {
            mma16816_f16(acc[mf][0], a[mf], bfr[0][0], bfr[0][2]);
            mma16816_f16(acc[mf][1], a[mf], bfr[0][1], bfr[0][3]);
            mma16816_f16(acc[mf][2], a[mf], bfr[1][0], bfr[1][2]);
            mma16816_f16(acc[mf][3], a[mf], bfr[1][1], bfr[1][3]);
        }
    }

    // ------- Epilogue: ex2.f16x2 directly on packed accs + row sums -------
    const int g  = lane >> 2;
    const int t4 = lane & 3;
    float rs0[4], rs1[4];
#pragma unroll
    for (int mf = 0; mf < 4; mf++) {
        uint32_t s0 = hadd2(hadd2(ex2h2(acc[mf][0][0]), ex2h2(acc[mf][1][0])),
                            hadd2(ex2h2(acc[mf][2][0]), ex2h2(acc[mf][3][0])));
        uint32_t s1 = hadd2(hadd2(ex2h2(acc[mf][0][1]), ex2h2(acc[mf][1][1])),
                            hadd2(ex2h2(acc[mf][2][1]), ex2h2(acc[mf][3][1])));
        rs0[mf] = unpack_sum(s0);              // row g
        rs1[mf] = unpack_sum(s1);              // row g+8
    }
#pragma unroll
    for (int mf = 0; mf < 4; mf++) {
        rs0[mf] += __shfl_xor_sync(0xffffffffu, rs0[mf], 1);
        rs0[mf] += __shfl_xor_sync(0xffffffffu, rs0[mf], 2);
        rs1[mf] += __shfl_xor_sync(0xffffffffu, rs1[mf], 1);
        rs1[mf] += __shfl_xor_sync(0xffffffffu, rs1[mf], 2);
    }

    __syncthreads();                           // tiles no longer needed; reuse smem
    float* red = (float*)smem;                 // [128 rows][4 wn]
    if (t4 == 0) {
#pragma unroll
        for (int mf = 0; mf < 4; mf++) {
            int r0 = wm * 64 + mf * 16 + g;
            red[r0 * 4 + wn]       = rs0[mf];
            red[(r0 + 8) * 4 + wn] = rs1[mf];
        }
    }
    __syncthreads();
    if (tid < 128) {
        float s = (red[tid * 4 + 0] + red[tid * 4 + 1]) +
                  (red[tid * 4 + 2] + red[tid * 4 + 3]);
        g_partial[(size_t)bn * NN + bm * 128 + tid] = s;   // fixed order, no atomics
    }
}

// ---------------------------------------------------------------------------
// Kernel 3: per-row total + loss + block sums, with fused final mean via
// deterministic last-block (threadfence + counter; sum order is fixed).
// ---------------------------------------------------------------------------
__global__ void reduce_kernel(float* __restrict__ out) {
    int r = blockIdx.x * blockDim.x + threadIdx.x;
    float t = 0.f;
#pragma unroll 8
    for (int cb = 0; cb < NN / 128; cb++) t += g_partial[(size_t)cb * NN + r];
    float lr = logf(t + EPS_F) - g_pos[r];

    __shared__ float sm[256];
    __shared__ int is_last;
    sm[threadIdx.x] = lr;
    __syncthreads();
    for (int o = 128; o; o >>= 1) {
        if (threadIdx.x < o) sm[threadIdx.x] += sm[threadIdx.x + o];
        __syncthreads();
    }
    if (threadIdx.x == 0) {
        g_blocksum[blockIdx.x] = sm[0];
        __threadfence();
        int old = atomicAdd(&g_done_cnt, 1);
        is_last = ((old & 63) == 63) ? 1 : 0;  // 64 blocks per launch; works across replays
    }
    __syncthreads();
    if (is_last && threadIdx.x < 64) {
        __threadfence();
        float v = g_blocksum[threadIdx.x];
#pragma unroll
        for (int o = 32; o; o >>= 1) v += __shfl_xor_sync(0xffffffffu, v, o);
        if (threadIdx.x == 0) out[0] = v * (1.0f / (float)NN);
    }
}

// ---------------------------------------------------------------------------
extern "C" void kernel_launch(void* const* d_in, const int* in_sizes, int n_in,
                              void* d_out, int out_size) {
    const float* U = (const float*)d_in[0];
    const float* I = (const float*)d_in[1];
    float* out = (float*)d_out;

    const int SMEM_BYTES = 2 * 128 * SROW;     // 32768
    cudaFuncSetAttribute(gemm_exp_kernel,
                         cudaFuncAttributeMaxDynamicSharedMemorySize, SMEM_BYTES);

    prep_kernel<<<NN / 8, 256>>>(U, I);

    dim3 grid(NN / 128, NN / 128);
    gemm_exp_kernel<<<grid, 256, SMEM_BYTES>>>();

    reduce_kernel<<<NN / 256, 256>>>(out);
}